// round 12
// baseline (speedup 1.0000x reference)
#include <cuda_runtime.h>
#include <cuda_bf16.h>

#define BB 2
#define TT 2048
#define HID 1024
#define NH 16
#define DD 64
#define NHTOT 48   // H + 2*HKV = 48 heads in qkv buffer

typedef unsigned long long u64;

// packed fp32x2 FMA: d = a*b + d (two independent fp32 lanes, full IEEE)
#define FMA2(d, a, b) asm("fma.rn.f32x2 %0, %1, %2, %0;" : "+l"(d) : "l"(a), "l"(b))

__device__ __forceinline__ u64 pack2(float lo, float hi) {
    u64 r; asm("mov.b64 %0, {%1, %2};" : "=l"(r) : "f"(lo), "f"(hi)); return r;
}
__device__ __forceinline__ float2 unpack2(u64 v) {
    float2 r; asm("mov.b64 {%0, %1}, %2;" : "=f"(r.x), "=f"(r.y) : "l"(v)); return r;
}

// Scratch (allocation-free rule: __device__ globals)
__device__ float g_qkv[BB * TT * NHTOT * DD];   // [b, t, head(48), d]
__device__ float g_ctx[BB * TT * NH * DD];      // [b, t, h*D]

// ---------------------------------------------------------------------------
// GEMM: C[m,n] = sum_k A[m,k] * W[n,k]   (unchanged)
// ---------------------------------------------------------------------------
__global__ __launch_bounds__(256) void gemm_tn_kernel(
    const float* __restrict__ A, const float* __restrict__ W,
    float* __restrict__ C, int M, int N, int K)
{
    __shared__ float As[16][132];
    __shared__ float Ws[16][132];

    const int tid = threadIdx.x;
    const int m0 = blockIdx.y * 128;
    const int n0 = blockIdx.x * 128;
    const int tx = tid % 16;
    const int ty = tid / 16;

    const int lr = tid / 4;
    const int lk = (tid % 4) * 4;

    u64 acc[8][4];
#pragma unroll
    for (int i = 0; i < 8; i++)
#pragma unroll
        for (int j = 0; j < 4; j++) acc[i][j] = 0ull;

    for (int k0 = 0; k0 < K; k0 += 16) {
#pragma unroll
        for (int r = 0; r < 2; r++) {
            int row = lr + r * 64;
            float4 a = *(const float4*)&A[(long)(m0 + row) * K + k0 + lk];
            As[lk + 0][row] = a.x; As[lk + 1][row] = a.y;
            As[lk + 2][row] = a.z; As[lk + 3][row] = a.w;
            float4 w = *(const float4*)&W[(long)(n0 + row) * K + k0 + lk];
            Ws[lk + 0][row] = w.x; Ws[lk + 1][row] = w.y;
            Ws[lk + 2][row] = w.z; Ws[lk + 3][row] = w.w;
        }
        __syncthreads();

#pragma unroll
        for (int kk = 0; kk < 16; kk++) {
            ulonglong2 w01 = *(const ulonglong2*)&Ws[kk][tx * 8];
            ulonglong2 w23 = *(const ulonglong2*)&Ws[kk][tx * 8 + 4];
            u64 wp0 = w01.x, wp1 = w01.y, wp2 = w23.x, wp3 = w23.y;
            float4 a03 = *(const float4*)&As[kk][ty * 8];
            float4 a47 = *(const float4*)&As[kk][ty * 8 + 4];
            float ar[8] = {a03.x, a03.y, a03.z, a03.w, a47.x, a47.y, a47.z, a47.w};
#pragma unroll
            for (int i = 0; i < 8; i++) {
                u64 ad = pack2(ar[i], ar[i]);
                FMA2(acc[i][0], ad, wp0);
                FMA2(acc[i][1], ad, wp1);
                FMA2(acc[i][2], ad, wp2);
                FMA2(acc[i][3], ad, wp3);
            }
        }
        __syncthreads();
    }

#pragma unroll
    for (int i = 0; i < 8; i++) {
        float* cp = &C[(long)(m0 + ty * 8 + i) * N + n0 + tx * 8];
#pragma unroll
        for (int j = 0; j < 2; j++) {
            float2 p0 = unpack2(acc[i][2 * j]);
            float2 p1 = unpack2(acc[i][2 * j + 1]);
            *(float4*)&cp[4 * j] = make_float4(p0.x, p0.y, p1.x, p1.y);
        }
    }
}

// ---------------------------------------------------------------------------
// RoPE in-place on q (heads 0..15) and k (heads 16..31) of g_qkv
// ---------------------------------------------------------------------------
__global__ void rope_kernel(const float* __restrict__ cosp, const float* __restrict__ sinp)
{
    int idx = blockIdx.x * blockDim.x + threadIdx.x;
    const int total = BB * TT * 32 * 32;
    if (idx >= total) return;
    int dh = idx % 32;
    int h  = (idx / 32) % 32;
    int bt = idx / (32 * 32);
    int t  = bt % TT;

    float* x = g_qkv + ((long)bt * NHTOT + h) * DD;
    float c1 = cosp[t * DD + dh],      s1 = sinp[t * DD + dh];
    float c2 = cosp[t * DD + dh + 32], s2 = sinp[t * DD + dh + 32];
    float x1 = x[dh], x2 = x[dh + 32];
    x[dh]      = x1 * c1 - x2 * s1;
    x[dh + 32] = x2 * c2 + x1 * s2;
}

// ---------------------------------------------------------------------------
// Deep-blocked flash attention: 128 threads, 128q x 64k tiles.
// QK: thread (qg=tid>>3, kg=tid&7) computes 8q x 8k (k split {4kg..,32+4kg..}).
//     Per kk: 2 LDS (q pairs) + 2 LDS (k) + 8 pack2 -> 32 FMA2.
// PV: thread (qg, dg=tid&7) computes 8q x 8d (d split likewise).
//     Per j:  2 LDS (p pairs, swizzled) + 2 LDS (v) + 8 pack2 -> 32 FMA2.
// Fixed-offset softmax exp(s-8); exact after o/l normalization.
// ---------------------------------------------------------------------------
#define QS_OFF  0                      // Qs [64][132]  d-major, scaled
#define KS_OFF  (64 * 132)             // Ks [64][68]   d-major (row d, col k)
#define VS_OFF  (KS_OFF + 64 * 68)     // Vs [64][68]   k-major (row k, col d)
#define PS_OFF  (VS_OFF + 64 * 68)     // Ps [64][132]  k-major, chunk-swizzled, packed-q
#define LR_OFF  (PS_OFF + 64 * 132)    // Lr [8][128]
#define SM_FLOATS (LR_OFF + 8 * 128)
#define SM_BYTES  (SM_FLOATS * 4)

__global__ __launch_bounds__(128, 2) void attn_kernel()
{
    extern __shared__ float sm[];
    float* Qs = sm + QS_OFF;
    float* Ks = sm + KS_OFF;
    float* Vs = sm + VS_OFF;
    float* Ps = sm + PS_OFF;
    float* Lr = sm + LR_OFF;

    const int tid = threadIdx.x;
    const int qt  = (gridDim.x - 1) - blockIdx.x;   // LPT: big blocks first
    const int qt0 = qt * 128;
    const int h   = blockIdx.y;
    const int b   = blockIdx.z;
    const int qg  = tid >> 3;       // 0..15: q rows 8qg..8qg+7
    const int kg  = tid & 7;        // 0..7:  k cols {4kg..+3, 32+4kg..+3} (PV: d cols)

    // ---- stage Q tile once: thread = one q row; scaled by 1/8, d-major ----
    {
        const float* qp = g_qkv + ((long)(b * TT + qt0 + tid) * NHTOT + h) * DD;
#pragma unroll
        for (int i = 0; i < 16; i++) {
            float4 v = ((const float4*)qp)[i];
            int d = 4 * i;
            Qs[(d + 0) * 132 + tid] = v.x * 0.125f;
            Qs[(d + 1) * 132 + tid] = v.y * 0.125f;
            Qs[(d + 2) * 132 + tid] = v.z * 0.125f;
            Qs[(d + 3) * 132 + tid] = v.w * 0.125f;
        }
    }

    // K/V staging lanes: 64 rows x 2 halves of d
    const int lrow = tid >> 1;      // key row 0..63
    const int half = tid & 1;       // d half
    const float* kbase = g_qkv + ((long)(b * TT + lrow) * NHTOT + NH + h) * DD + 32 * half;
    const float* vbase = g_qkv + ((long)(b * TT + lrow) * NHTOT + 2 * NH + h) * DD + 32 * half;
    const long kv_step = (long)64 * NHTOT * DD;   // advance 64 key rows

    u64 s2[4][8];                   // [qpair][kcol]
    u64 o2[4][8];                   // [qpair][dcol]
    float lp[8];
#pragma unroll
    for (int i = 0; i < 4; i++)
#pragma unroll
        for (int j = 0; j < 8; j++) { s2[i][j] = 0ull; o2[i][j] = 0ull; }
#pragma unroll
    for (int i = 0; i < 8; i++) lp[i] = 0.f;

    const int ntiles = 2 * qt + 2;

    for (int kt = 0; kt < ntiles; kt++) {
        const int k0 = kt * 64;

        // ---- stage K (d-major) and V (k-major) ----
        {
            const float* kp = kbase + (long)kt * kv_step;
            const float* vp = vbase + (long)kt * kv_step;
#pragma unroll
            for (int i = 0; i < 8; i++) {
                float4 kv = ((const float4*)kp)[i];
                int d = 32 * half + 4 * i;
                Ks[(d + 0) * 68 + lrow] = kv.x;
                Ks[(d + 1) * 68 + lrow] = kv.y;
                Ks[(d + 2) * 68 + lrow] = kv.z;
                Ks[(d + 3) * 68 + lrow] = kv.w;
                float4 vv = ((const float4*)vp)[i];
                *(float4*)&Vs[lrow * 68 + d] = vv;
            }
        }
        __syncthreads();   // K,V (and Qs on first iter) ready

        // ---- QK: 8q x 8k per thread ----
#pragma unroll 8
        for (int kk = 0; kk < 64; kk++) {
            ulonglong2 qA = *(const ulonglong2*)&Qs[kk * 132 + 8 * qg];       // qpairs 0,1
            ulonglong2 qB = *(const ulonglong2*)&Qs[kk * 132 + 8 * qg + 4];   // qpairs 2,3
            float4 ka = *(const float4*)&Ks[kk * 68 + 4 * kg];
            float4 kb = *(const float4*)&Ks[kk * 68 + 32 + 4 * kg];
            u64 kd0 = pack2(ka.x, ka.x), kd1 = pack2(ka.y, ka.y);
            u64 kd2 = pack2(ka.z, ka.z), kd3 = pack2(ka.w, ka.w);
            u64 kd4 = pack2(kb.x, kb.x), kd5 = pack2(kb.y, kb.y);
            u64 kd6 = pack2(kb.z, kb.z), kd7 = pack2(kb.w, kb.w);
            FMA2(s2[0][0], qA.x, kd0); FMA2(s2[1][0], qA.y, kd0);
            FMA2(s2[2][0], qB.x, kd0); FMA2(s2[3][0], qB.y, kd0);
            FMA2(s2[0][1], qA.x, kd1); FMA2(s2[1][1], qA.y, kd1);
            FMA2(s2[2][1], qB.x, kd1); FMA2(s2[3][1], qB.y, kd1);
            FMA2(s2[0][2], qA.x, kd2); FMA2(s2[1][2], qA.y, kd2);
            FMA2(s2[2][2], qB.x, kd2); FMA2(s2[3][2], qB.y, kd2);
            FMA2(s2[0][3], qA.x, kd3); FMA2(s2[1][3], qA.y, kd3);
            FMA2(s2[2][3], qB.x, kd3); FMA2(s2[3][3], qB.y, kd3);
            FMA2(s2[0][4], qA.x, kd4); FMA2(s2[1][4], qA.y, kd4);
            FMA2(s2[2][4], qB.x, kd4); FMA2(s2[3][4], qB.y, kd4);
            FMA2(s2[0][5], qA.x, kd5); FMA2(s2[1][5], qA.y, kd5);
            FMA2(s2[2][5], qB.x, kd5); FMA2(s2[3][5], qB.y, kd5);
            FMA2(s2[0][6], qA.x, kd6); FMA2(s2[1][6], qA.y, kd6);
            FMA2(s2[2][6], qB.x, kd6); FMA2(s2[3][6], qB.y, kd6);
            FMA2(s2[0][7], qA.x, kd7); FMA2(s2[1][7], qA.y, kd7);
            FMA2(s2[2][7], qB.x, kd7); FMA2(s2[3][7], qB.y, kd7);
        }

        // ---- exp + mask + Ps write (swizzled, packed-q) + lp; zero s2 ----
        const bool masked = (kt >= 2 * qt);
#pragma unroll
        for (int kc = 0; kc < 8; kc++) {
            int krow = 4 * kg + (kc & 3) + 32 * (kc >> 2);
            int kglob = k0 + krow;
            u64 pp[4];
#pragma unroll
            for (int qp = 0; qp < 4; qp++) {
                float2 sv = unpack2(s2[qp][kc]);
                s2[qp][kc] = 0ull;
                float p0 = __expf(sv.x - 8.0f);
                float p1 = __expf(sv.y - 8.0f);
                if (masked) {
                    int q = qt0 + 8 * qg + 2 * qp;
                    if (kglob > q)     p0 = 0.f;
                    if (kglob > q + 1) p1 = 0.f;
                }
                lp[2 * qp]     += p0;
                lp[2 * qp + 1] += p1;
                pp[qp] = pack2(p0, p1);
            }
            int sw = (2 * krow) & 31;
            int cs0 = (2 * qg)     ^ sw;
            int cs1 = (2 * qg + 1) ^ sw;
            ulonglong2 w0; w0.x = pp[0]; w0.y = pp[1];
            ulonglong2 w1; w1.x = pp[2]; w1.y = pp[3];
            *(ulonglong2*)&Ps[krow * 132 + 4 * cs0] = w0;
            *(ulonglong2*)&Ps[krow * 132 + 4 * cs1] = w1;
        }
        __syncthreads();   // P ready

        // ---- PV: 8q x 8d per thread (dg = kg lanes) ----
#pragma unroll 8
        for (int j = 0; j < 64; j++) {
            int sw = (2 * j) & 31;
            ulonglong2 pA = *(const ulonglong2*)&Ps[j * 132 + 4 * ((2 * qg) ^ sw)];
            ulonglong2 pB = *(const ulonglong2*)&Ps[j * 132 + 4 * ((2 * qg + 1) ^ sw)];
            float4 va = *(const float4*)&Vs[j * 68 + 4 * kg];
            float4 vb = *(const float4*)&Vs[j * 68 + 32 + 4 * kg];
            u64 vd0 = pack2(va.x, va.x), vd1 = pack2(va.y, va.y);
            u64 vd2 = pack2(va.z, va.z), vd3 = pack2(va.w, va.w);
            u64 vd4 = pack2(vb.x, vb.x), vd5 = pack2(vb.y, vb.y);
            u64 vd6 = pack2(vb.z, vb.z), vd7 = pack2(vb.w, vb.w);
            FMA2(o2[0][0], pA.x, vd0); FMA2(o2[1][0], pA.y, vd0);
            FMA2(o2[2][0], pB.x, vd0); FMA2(o2[3][0], pB.y, vd0);
            FMA2(o2[0][1], pA.x, vd1); FMA2(o2[1][1], pA.y, vd1);
            FMA2(o2[2][1], pB.x, vd1); FMA2(o2[3][1], pB.y, vd1);
            FMA2(o2[0][2], pA.x, vd2); FMA2(o2[1][2], pA.y, vd2);
            FMA2(o2[2][2], pB.x, vd2); FMA2(o2[3][2], pB.y, vd2);
            FMA2(o2[0][3], pA.x, vd3); FMA2(o2[1][3], pA.y, vd3);
            FMA2(o2[2][3], pB.x, vd3); FMA2(o2[3][3], pB.y, vd3);
            FMA2(o2[0][4], pA.x, vd4); FMA2(o2[1][4], pA.y, vd4);
            FMA2(o2[2][4], pB.x, vd4); FMA2(o2[3][4], pB.y, vd4);
            FMA2(o2[0][5], pA.x, vd5); FMA2(o2[1][5], pA.y, vd5);
            FMA2(o2[2][5], pB.x, vd5); FMA2(o2[3][5], pB.y, vd5);
            FMA2(o2[0][6], pA.x, vd6); FMA2(o2[1][6], pA.y, vd6);
            FMA2(o2[2][6], pB.x, vd6); FMA2(o2[3][6], pB.y, vd6);
            FMA2(o2[0][7], pA.x, vd7); FMA2(o2[1][7], pA.y, vd7);
            FMA2(o2[2][7], pB.x, vd7); FMA2(o2[3][7], pB.y, vd7);
        }
        __syncthreads();   // PV done; safe to overwrite K/V/P
    }

    // ---- l reduction across the 8 kg groups ----
#pragma unroll
    for (int qq = 0; qq < 8; qq++) Lr[kg * 128 + 8 * qg + qq] = lp[qq];
    __syncthreads();

    // ---- normalize + write: thread (qg, dg=kg) owns 8q x 8d ----
#pragma unroll
    for (int qp = 0; qp < 4; qp++) {
        float2 ov[8];
#pragma unroll
        for (int dc = 0; dc < 8; dc++) ov[dc] = unpack2(o2[qp][dc]);
#pragma unroll
        for (int e = 0; e < 2; e++) {
            int q = 8 * qg + 2 * qp + e;
            float s = 0.f;
#pragma unroll
            for (int x = 0; x < 8; x++) s += Lr[x * 128 + q];
            float inv = 1.f / s;
            float* op = g_ctx + ((long)(b * TT + qt0 + q)) * (NH * DD) + h * DD;
            float v0 = (e ? ov[0].y : ov[0].x) * inv;
            float v1 = (e ? ov[1].y : ov[1].x) * inv;
            float v2 = (e ? ov[2].y : ov[2].x) * inv;
            float v3 = (e ? ov[3].y : ov[3].x) * inv;
            float v4 = (e ? ov[4].y : ov[4].x) * inv;
            float v5 = (e ? ov[5].y : ov[5].x) * inv;
            float v6 = (e ? ov[6].y : ov[6].x) * inv;
            float v7 = (e ? ov[7].y : ov[7].x) * inv;
            *(float4*)&op[4 * kg]      = make_float4(v0, v1, v2, v3);
            *(float4*)&op[32 + 4 * kg] = make_float4(v4, v5, v6, v7);
        }
    }
}

// ---------------------------------------------------------------------------
extern "C" void kernel_launch(void* const* d_in, const int* in_sizes, int n_in,
                              void* d_out, int out_size)
{
    const float* hidden = (const float*)d_in[0];   // [B,T,HID]
    const float* cosp   = (const float*)d_in[1];   // [T,D]
    const float* sinp   = (const float*)d_in[2];   // [T,D]
    const float* w_qkv  = (const float*)d_in[3];   // [3072,1024]
    const float* w_o    = (const float*)d_in[4];   // [1024,1024]
    float* out = (float*)d_out;                    // [B,T,HID]

    float *qkv_ptr, *ctx_ptr;
    cudaGetSymbolAddress((void**)&qkv_ptr, g_qkv);
    cudaGetSymbolAddress((void**)&ctx_ptr, g_ctx);

    // Host-side attribute set (not a stream op; safe under graph capture).
    cudaFuncSetAttribute(attn_kernel,
                         cudaFuncAttributeMaxDynamicSharedMemorySize, SM_BYTES);

    const int M = BB * TT;           // 4096
    const int Nqkv = NHTOT * DD;     // 3072

    // 1) QKV projection
    {
        dim3 grid(Nqkv / 128, M / 128);
        gemm_tn_kernel<<<grid, 256>>>(hidden, w_qkv, qkv_ptr, M, Nqkv, HID);
    }
    // 2) RoPE on q,k
    {
        int total = BB * TT * 32 * 32;
        rope_kernel<<<(total + 255) / 256, 256>>>(cosp, sinp);
    }
    // 3) Causal flash attention (deep-blocked)
    {
        dim3 grid(TT / 128, NH, BB);
        attn_kernel<<<grid, 128, SM_BYTES>>>();
    }
    // 4) Output projection
    {
        dim3 grid(HID / 128, M / 128);
        gemm_tn_kernel<<<grid, 256>>>(ctx_ptr, w_o, out, M, HID, HID);
    }
}

// round 15
// speedup vs baseline: 1.7563x; 1.7563x over previous
#include <cuda_runtime.h>
#include <cuda_bf16.h>
#include <cstdint>

#define BB 2
#define TT 2048
#define HID 1024
#define NH 16
#define DD 64
#define NHTOT 48   // H + 2*HKV = 48 heads in qkv buffer

typedef unsigned long long u64;

// packed fp32x2 FMA: d = a*b + d (two independent fp32 lanes, full IEEE)
#define FMA2(d, a, b) asm("fma.rn.f32x2 %0, %1, %2, %0;" : "+l"(d) : "l"(a), "l"(b))

__device__ __forceinline__ u64 pack2(float lo, float hi) {
    u64 r; asm("mov.b64 %0, {%1, %2};" : "=l"(r) : "f"(lo), "f"(hi)); return r;
}
__device__ __forceinline__ float2 unpack2(u64 v) {
    float2 r; asm("mov.b64 {%0, %1}, %2;" : "=f"(r.x), "=f"(r.y) : "l"(v)); return r;
}
__device__ __forceinline__ uint32_t f2tf32(float f) {
    uint32_t u; asm("cvt.rna.tf32.f32 %0, %1;" : "=r"(u) : "f"(f)); return u;
}

// Scratch (allocation-free rule: __device__ globals)
__device__ float g_qkv[BB * TT * NHTOT * DD];   // [b, t, head(48), d]
__device__ float g_ctx[BB * TT * NH * DD];      // [b, t, h*D]

// ---------------------------------------------------------------------------
// tf32 tensor-core GEMM: C[m,n] = sum_k A[m,k] * W[n,k]
// Block 128x128, k-chunk 32, 256 threads = 8 warps (4m x 2n), warp = 32m x 64n.
// mma.sync.aligned.m16n8k8.row.col.f32.tf32.tf32.f32
// Smem row-major with pad 36 (conflict-free fragment gathers).
// ---------------------------------------------------------------------------
__global__ __launch_bounds__(256) void gemm_mma_kernel(
    const float* __restrict__ A, const float* __restrict__ W,
    float* __restrict__ C, int M, int N, int K)
{
    __shared__ uint32_t As[128 * 36];
    __shared__ uint32_t Ws[128 * 36];

    const int tid  = threadIdx.x;
    const int lane = tid & 31;
    const int warp = tid >> 5;
    const int g    = lane >> 2;      // groupID 0..7
    const int t    = lane & 3;       // thread-in-group 0..3
    const int mw   = (warp & 3) * 32;   // warp m offset
    const int nw   = (warp >> 2) * 64;  // warp n offset
    const int m0   = blockIdx.y * 128;
    const int n0   = blockIdx.x * 128;

    float acc[2][8][4];
#pragma unroll
    for (int mf = 0; mf < 2; mf++)
#pragma unroll
        for (int nf = 0; nf < 8; nf++)
#pragma unroll
            for (int e = 0; e < 4; e++) acc[mf][nf][e] = 0.f;

    for (int k0 = 0; k0 < K; k0 += 32) {
        // ---- stage A and W chunks (converted to tf32 bits) ----
#pragma unroll
        for (int i = 0; i < 4; i++) {
            int idx = tid + 256 * i;          // float4 index 0..1023
            int row = idx >> 3;
            int c4  = (idx & 7) * 4;
            float4 a = *(const float4*)&A[(long)(m0 + row) * K + k0 + c4];
            uint4 ua = make_uint4(f2tf32(a.x), f2tf32(a.y), f2tf32(a.z), f2tf32(a.w));
            *(uint4*)&As[row * 36 + c4] = ua;
            float4 w = *(const float4*)&W[(long)(n0 + row) * K + k0 + c4];
            uint4 uw = make_uint4(f2tf32(w.x), f2tf32(w.y), f2tf32(w.z), f2tf32(w.w));
            *(uint4*)&Ws[row * 36 + c4] = uw;
        }
        __syncthreads();

#pragma unroll
        for (int ks = 0; ks < 4; ks++) {
            const int kk = ks * 8 + t;
            // B fragments for 8 n-frags
            uint32_t bf[8][2];
#pragma unroll
            for (int nf = 0; nf < 8; nf++) {
                int n = nw + nf * 8 + g;
                bf[nf][0] = Ws[n * 36 + kk];
                bf[nf][1] = Ws[n * 36 + kk + 4];
            }
#pragma unroll
            for (int mf = 0; mf < 2; mf++) {
                int m = mw + mf * 16 + g;
                uint32_t a0 = As[m * 36 + kk];
                uint32_t a1 = As[(m + 8) * 36 + kk];
                uint32_t a2 = As[m * 36 + kk + 4];
                uint32_t a3 = As[(m + 8) * 36 + kk + 4];
#pragma unroll
                for (int nf = 0; nf < 8; nf++) {
                    asm volatile(
                        "mma.sync.aligned.m16n8k8.row.col.f32.tf32.tf32.f32 "
                        "{%0,%1,%2,%3}, {%4,%5,%6,%7}, {%8,%9}, {%0,%1,%2,%3};"
                        : "+f"(acc[mf][nf][0]), "+f"(acc[mf][nf][1]),
                          "+f"(acc[mf][nf][2]), "+f"(acc[mf][nf][3])
                        : "r"(a0), "r"(a1), "r"(a2), "r"(a3),
                          "r"(bf[nf][0]), "r"(bf[nf][1]));
                }
            }
        }
        __syncthreads();
    }

    // ---- epilogue ----
#pragma unroll
    for (int mf = 0; mf < 2; mf++) {
        int row = m0 + mw + mf * 16 + g;
#pragma unroll
        for (int nf = 0; nf < 8; nf++) {
            int col = n0 + nw + nf * 8 + 2 * t;
            *(float2*)&C[(long)row * N + col] =
                make_float2(acc[mf][nf][0], acc[mf][nf][1]);
            *(float2*)&C[(long)(row + 8) * N + col] =
                make_float2(acc[mf][nf][2], acc[mf][nf][3]);
        }
    }
}

// ---------------------------------------------------------------------------
// RoPE in-place on q (heads 0..15) and k (heads 16..31) of g_qkv
// ---------------------------------------------------------------------------
__global__ void rope_kernel(const float* __restrict__ cosp, const float* __restrict__ sinp)
{
    int idx = blockIdx.x * blockDim.x + threadIdx.x;
    const int total = BB * TT * 32 * 32;
    if (idx >= total) return;
    int dh = idx % 32;
    int h  = (idx / 32) % 32;
    int bt = idx / (32 * 32);
    int t  = bt % TT;

    float* x = g_qkv + ((long)bt * NHTOT + h) * DD;
    float c1 = cosp[t * DD + dh],      s1 = sinp[t * DD + dh];
    float c2 = cosp[t * DD + dh + 32], s2 = sinp[t * DD + dh + 32];
    float x1 = x[dh], x2 = x[dh + 32];
    x[dh]      = x1 * c1 - x2 * s1;
    x[dh + 32] = x2 * c2 + x1 * s2;
}

// ---------------------------------------------------------------------------
// GEMM-structured flash attention (R7 record version, unchanged).
// ---------------------------------------------------------------------------
#define QS_OFF  0                    // Qs [64][132]  d-major, scaled
#define KS_OFF  (64 * 132)           // Ks [64][32]   d-major, chunk-swizzled
#define VS_OFF  (KS_OFF + 64 * 32)   // Vs [32][64]   k-major
#define PS_OFF  (VS_OFF + 32 * 64)   // Ps [32][132]  k-major, chunk-swizzled
#define LR_OFF  (PS_OFF + 32 * 132)  // Lr [8][128]
#define SM_FLOATS (LR_OFF + 8 * 128)
#define SM_BYTES  (SM_FLOATS * 4)

__global__ __launch_bounds__(256) void attn_kernel()
{
    extern __shared__ float sm[];
    float* Qs = sm + QS_OFF;
    float* Ks = sm + KS_OFF;
    float* Vs = sm + VS_OFF;
    float* Ps = sm + PS_OFF;
    float* Lr = sm + LR_OFF;

    const int tid = threadIdx.x;
    const int qt  = (gridDim.x - 1) - blockIdx.x;   // LPT: big blocks first
    const int qt0 = qt * 128;
    const int h   = blockIdx.y;
    const int b   = blockIdx.z;
    const int tx  = tid & 7;        // k-col group (QK) / d-col group (PV)
    const int ty  = tid >> 3;       // q-row group, 0..31

    // ---- load Q tile, scaled by 1/8, transposed to d-major ----
    {
        int q  = tid >> 1;
        int d0 = (tid & 1) * 32;
        const float* qp = g_qkv + ((long)(b * TT + qt0 + q) * NHTOT + h) * DD + d0;
#pragma unroll
        for (int i = 0; i < 8; i++) {
            float4 v = ((const float4*)qp)[i];
            int d = d0 + 4 * i;
            Qs[(d + 0) * 132 + q] = v.x * 0.125f;
            Qs[(d + 1) * 132 + q] = v.y * 0.125f;
            Qs[(d + 2) * 132 + q] = v.z * 0.125f;
            Qs[(d + 3) * 132 + q] = v.w * 0.125f;
        }
    }

    u64 o[4][4];
#pragma unroll
    for (int i = 0; i < 4; i++)
#pragma unroll
        for (int j = 0; j < 4; j++) o[i][j] = 0ull;
    float lp[4] = {0.f, 0.f, 0.f, 0.f};

    const int ntiles = (qt0 + 128) / 32;
    const int mask_start = qt0 / 32;

    for (int kt = 0; kt < ntiles; kt++) {
        const int k0 = kt * 32;

        // ---- load K (d-major, chunk-swizzled) and V (k-major) ----
        {
            int k  = tid >> 3;
            int dg = tid & 7;
            const float* kp = g_qkv + ((long)(b * TT + k0 + k) * NHTOT + NH + h) * DD + dg * 8;
            const float* vp = g_qkv + ((long)(b * TT + k0 + k) * NHTOT + 2 * NH + h) * DD + dg * 8;
            int kch = ((k >> 2) ^ dg) * 4 + (k & 3);
#pragma unroll
            for (int u = 0; u < 2; u++) {
                float4 kv = ((const float4*)kp)[u];
                int d = dg * 8 + u * 4;
                Ks[(d + 0) * 32 + kch] = kv.x;
                Ks[(d + 1) * 32 + kch] = kv.y;
                Ks[(d + 2) * 32 + kch] = kv.z;
                Ks[(d + 3) * 32 + kch] = kv.w;
                float4 vv = ((const float4*)vp)[u];
                *(float4*)&Vs[k * 64 + d] = vv;
            }
        }
        __syncthreads();

        // ---- QK: S(4q x 4k) ----
        u64 sq0[4] = {0, 0, 0, 0};
        u64 sq1[4] = {0, 0, 0, 0};
#pragma unroll 16
        for (int kk = 0; kk < 64; kk++) {
            ulonglong2 qp2 = *(const ulonglong2*)&Qs[kk * 132 + 4 * ty];
            float4 kv = *(const float4*)&Ks[kk * 32 + ((tx ^ (kk >> 3)) << 2)];
            u64 b0 = pack2(kv.x, kv.x);
            u64 b1 = pack2(kv.y, kv.y);
            u64 b2 = pack2(kv.z, kv.z);
            u64 b3 = pack2(kv.w, kv.w);
            FMA2(sq0[0], qp2.x, b0); FMA2(sq1[0], qp2.y, b0);
            FMA2(sq0[1], qp2.x, b1); FMA2(sq1[1], qp2.y, b1);
            FMA2(sq0[2], qp2.x, b2); FMA2(sq1[2], qp2.y, b2);
            FMA2(sq0[3], qp2.x, b3); FMA2(sq1[3], qp2.y, b3);
        }

        // ---- exp + mask + P write (swizzled) + l partials ----
        const bool masked = (kt >= mask_start);
        const int pch = 4 * (ty ^ (tx & 3));
#pragma unroll
        for (int cc = 0; cc < 4; cc++) {
            float2 s01 = unpack2(sq0[cc]);
            float2 s23 = unpack2(sq1[cc]);
            float p0 = __expf(s01.x - 8.0f);
            float p1 = __expf(s01.y - 8.0f);
            float p2 = __expf(s23.x - 8.0f);
            float p3 = __expf(s23.y - 8.0f);
            if (masked) {
                int c = k0 + 4 * tx + cc;
                int q = qt0 + 4 * ty;
                if (c > q + 0) p0 = 0.f;
                if (c > q + 1) p1 = 0.f;
                if (c > q + 2) p2 = 0.f;
                if (c > q + 3) p3 = 0.f;
            }
            lp[0] += p0; lp[1] += p1; lp[2] += p2; lp[3] += p3;
            *(float4*)&Ps[(4 * tx + cc) * 132 + pch] = make_float4(p0, p1, p2, p3);
        }
        __syncthreads();

        // ---- PV: O(4q x 8d) ----
#pragma unroll 8
        for (int j = 0; j < 32; j++) {
            float4 pj = *(const float4*)&Ps[j * 132 + 4 * (ty ^ ((j >> 2) & 3))];
            ulonglong2 v0 = *(const ulonglong2*)&Vs[j * 64 + 4 * tx];
            ulonglong2 v1 = *(const ulonglong2*)&Vs[j * 64 + 32 + 4 * tx];
            u64 p0 = pack2(pj.x, pj.x);
            u64 p1 = pack2(pj.y, pj.y);
            u64 p2 = pack2(pj.z, pj.z);
            u64 p3 = pack2(pj.w, pj.w);
            FMA2(o[0][0], p0, v0.x); FMA2(o[0][1], p0, v0.y);
            FMA2(o[0][2], p0, v1.x); FMA2(o[0][3], p0, v1.y);
            FMA2(o[1][0], p1, v0.x); FMA2(o[1][1], p1, v0.y);
            FMA2(o[1][2], p1, v1.x); FMA2(o[1][3], p1, v1.y);
            FMA2(o[2][0], p2, v0.x); FMA2(o[2][1], p2, v0.y);
            FMA2(o[2][2], p2, v1.x); FMA2(o[2][3], p2, v1.y);
            FMA2(o[3][0], p3, v0.x); FMA2(o[3][1], p3, v0.y);
            FMA2(o[3][2], p3, v1.x); FMA2(o[3][3], p3, v1.y);
        }
        __syncthreads();
    }

    // ---- row-sum reduction across the 8 tx threads ----
#pragma unroll
    for (int rr = 0; rr < 4; rr++) Lr[tx * 128 + 4 * ty + rr] = lp[rr];
    __syncthreads();

#pragma unroll
    for (int rr = 0; rr < 4; rr++) {
        float s = 0.f;
#pragma unroll
        for (int x = 0; x < 8; x++) s += Lr[x * 128 + 4 * ty + rr];
        float inv = 1.f / s;

        float2 a0 = unpack2(o[rr][0]);
        float2 a1 = unpack2(o[rr][1]);
        float2 a2 = unpack2(o[rr][2]);
        float2 a3 = unpack2(o[rr][3]);
        float* op = g_ctx + ((long)(b * TT + qt0 + 4 * ty + rr)) * (NH * DD) + h * DD;
        *(float4*)&op[4 * tx]      = make_float4(a0.x * inv, a0.y * inv, a1.x * inv, a1.y * inv);
        *(float4*)&op[32 + 4 * tx] = make_float4(a2.x * inv, a2.y * inv, a3.x * inv, a3.y * inv);
    }
}

// ---------------------------------------------------------------------------
extern "C" void kernel_launch(void* const* d_in, const int* in_sizes, int n_in,
                              void* d_out, int out_size)
{
    const float* hidden = (const float*)d_in[0];   // [B,T,HID]
    const float* cosp   = (const float*)d_in[1];   // [T,D]
    const float* sinp   = (const float*)d_in[2];   // [T,D]
    const float* w_qkv  = (const float*)d_in[3];   // [3072,1024]
    const float* w_o    = (const float*)d_in[4];   // [1024,1024]
    float* out = (float*)d_out;                    // [B,T,HID]

    float *qkv_ptr, *ctx_ptr;
    cudaGetSymbolAddress((void**)&qkv_ptr, g_qkv);
    cudaGetSymbolAddress((void**)&ctx_ptr, g_ctx);

    // Host-side attribute set (not a stream op; safe under graph capture).
    cudaFuncSetAttribute(attn_kernel,
                         cudaFuncAttributeMaxDynamicSharedMemorySize, SM_BYTES);

    const int M = BB * TT;           // 4096
    const int Nqkv = NHTOT * DD;     // 3072

    // 1) QKV projection (tf32 tensor cores)
    {
        dim3 grid(Nqkv / 128, M / 128);
        gemm_mma_kernel<<<grid, 256>>>(hidden, w_qkv, qkv_ptr, M, Nqkv, HID);
    }
    // 2) RoPE on q,k
    {
        int total = BB * TT * 32 * 32;
        rope_kernel<<<(total + 255) / 256, 256>>>(cosp, sinp);
    }
    // 3) Causal flash attention (fp32 SIMT, R7 record version)
    {
        dim3 grid(TT / 128, NH, BB);
        attn_kernel<<<grid, 256, SM_BYTES>>>();
    }
    // 4) Output projection (tf32 tensor cores)
    {
        dim3 grid(HID / 128, M / 128);
        gemm_mma_kernel<<<grid, 256>>>(ctx_ptr, w_o, out, M, HID, HID);
    }
}